// round 10
// baseline (speedup 1.0000x reference)
#include <cuda_runtime.h>

#define DD 13
#define HH 32
#define FF 45
#define XP 16
#define K1 64
#define GG 128
#define NMAX 50000
#define WABROW 92
#define TILE 128
#define H1STRIDE 68   // 68%32==4 -> conflict-free LDS.128 across lanes

typedef unsigned long long ull;
typedef unsigned int u32;

// ---------------- device scratch ----------------
__device__ float g_sum[DD];
__device__ float g_sumsq[DD];
__device__ float g_mean[DD];
__device__ float g_istd[DD];
__device__ float g_X[NMAX * XP];
__device__ float g_u[NMAX * K1];
__device__ float g_v[NMAX * K1];
__device__ float g_acc[NMAX * HH];
__device__ float g_wab[K1 * WABROW];
__device__ float g_gsum[GG * (HH + XP)];
__device__ int   g_gcnt[GG];

// ---------------- helpers ----------------
__device__ __forceinline__ float tanh_fast(float x) {
    float y; asm("tanh.approx.f32 %0, %1;" : "=f"(y) : "f"(x)); return y;
}
__device__ __forceinline__ void red_add_v4(float* p, float a, float b, float c, float d) {
    asm volatile("red.global.add.v4.f32 [%0], {%1, %2, %3, %4};"
                 :: "l"(p), "f"(a), "f"(b), "f"(c), "f"(d) : "memory");
}
__device__ __forceinline__ ull pack2(float x) {
    ull r; asm("mov.b64 %0, {%1, %1};" : "=l"(r) : "r"(__float_as_uint(x))); return r;
}
__device__ __forceinline__ void ffma2(ull& d, ull a, ull b) {
    asm("fma.rn.f32x2 %0, %1, %2, %0;" : "+l"(d) : "l"(a), "l"(b));
}
__device__ __forceinline__ ull add2(ull a, ull b) {
    ull r; asm("add.rn.f32x2 %0, %1, %2;" : "=l"(r) : "l"(a), "l"(b)); return r;
}
__device__ __forceinline__ void unpack2(ull v, float& lo, float& hi) {
    u32 a, b; asm("mov.b64 {%0, %1}, %2;" : "=r"(a), "=r"(b) : "l"(v));
    lo = __uint_as_float(a); hi = __uint_as_float(b);
}

// ---------------- 1) small zero ----------------
__global__ void zero_kernel() {
    int i = threadIdx.x;
    if (i < DD) { g_sum[i] = 0.f; g_sumsq[i] = 0.f; }
    for (int j = i; j < GG * (HH + XP); j += blockDim.x) g_gsum[j] = 0.f;
    if (i < GG) g_gcnt[i] = 0;
}

// ---------------- 2) batchnorm statistics ----------------
__global__ void bn_stats(const float* __restrict__ x, int n) {
    float s[DD], s2[DD];
#pragma unroll
    for (int d = 0; d < DD; d++) { s[d] = 0.f; s2[d] = 0.f; }
    for (int i = blockIdx.x * blockDim.x + threadIdx.x; i < n;
         i += gridDim.x * blockDim.x) {
#pragma unroll
        for (int d = 0; d < DD; d++) {
            float v = x[i * DD + d];
            s[d] += v; s2[d] += v * v;
        }
    }
#pragma unroll
    for (int d = 0; d < DD; d++) {
        for (int off = 16; off > 0; off >>= 1) {
            s[d]  += __shfl_down_sync(0xffffffffu, s[d], off);
            s2[d] += __shfl_down_sync(0xffffffffu, s2[d], off);
        }
    }
    if ((threadIdx.x & 31) == 0) {
#pragma unroll
        for (int d = 0; d < DD; d++) {
            atomicAdd(&g_sum[d], s[d]);
            atomicAdd(&g_sumsq[d], s2[d]);
        }
    }
}

// ---------------- 3) prep: stats + interleaved combined conv_w1 ----------------
__global__ void prep_kernel(const float* __restrict__ conv_w1, float invN) {
    int tid = threadIdx.x;
    if (tid < DD) {
        float mu  = g_sum[tid] * invN;
        float var = g_sumsq[tid] * invN - mu * mu;
        g_mean[tid] = mu;
        g_istd[tid] = rsqrtf(var + 1e-5f);
    }
    for (int i = tid; i < K1 * (WABROW / 2); i += blockDim.x) {
        int k = i / (WABROW / 2), a = i % (WABROW / 2);
        float wa = 0.f, wb = 0.f;
        if (a < FF) {
            float w0 = conv_w1[a * K1 + k];
            float w1 = conv_w1[(FF + a) * K1 + k];
            wa = w0 - w1; wb = w1;
        }
        g_wab[k * WABROW + 2 * a]     = wa;
        g_wab[k * WABROW + 2 * a + 1] = wb;
    }
}

// ---------------- 4) node kernel: 2 threads per node (k-split u/v) ----------------
__global__ void __launch_bounds__(256)
node_kernel(const float* __restrict__ x,
            const float* __restrict__ gamma,
            const float* __restrict__ beta,
            const float* __restrict__ w1,
            const float* __restrict__ b1,
            const float* __restrict__ w2,
            const float* __restrict__ b2,
            const float* __restrict__ conv_b1,
            int n) {
    __shared__ float s_w1[DD * HH], s_w2[HH * HH], s_b1[HH], s_b2[HH];
    __shared__ float s_gam[DD], s_bet[DD], s_mu[DD], s_is[DD];
    __shared__ float s_wab[K1 * WABROW];
    __shared__ ull   s_cbp[K1];
    for (int i = threadIdx.x; i < DD * HH; i += blockDim.x) s_w1[i] = w1[i];
    for (int i = threadIdx.x; i < HH * HH; i += blockDim.x) s_w2[i] = w2[i];
    for (int i = threadIdx.x; i < K1 * WABROW; i += blockDim.x) s_wab[i] = g_wab[i];
    if (threadIdx.x < K1)
        s_cbp[threadIdx.x] = (ull)__float_as_uint(conv_b1[threadIdx.x]);
    if (threadIdx.x < HH) { s_b1[threadIdx.x] = b1[threadIdx.x]; s_b2[threadIdx.x] = b2[threadIdx.x]; }
    if (threadIdx.x < DD) {
        s_gam[threadIdx.x] = gamma[threadIdx.x];
        s_bet[threadIdx.x] = beta[threadIdx.x];
        s_mu[threadIdx.x]  = g_mean[threadIdx.x];
        s_is[threadIdx.x]  = g_istd[threadIdx.x];
    }
    __syncthreads();
    int t = blockIdx.x * blockDim.x + threadIdx.x;
    int nn = t >> 1;
    int half = t & 1;
    if (nn >= n) return;

    float X[DD];
#pragma unroll
    for (int d = 0; d < DD; d++)
        X[d] = (x[nn * DD + d] - s_mu[d]) * s_is[d] * s_gam[d] + s_bet[d];

    float h[HH];
#pragma unroll
    for (int j = 0; j < HH; j++) {
        float tt = s_b1[j];
#pragma unroll
        for (int d = 0; d < DD; d++) tt = fmaf(X[d], s_w1[d * HH + j], tt);
        h[j] = fmaxf(tt, 0.f);
    }
    ull fp[FF];
#pragma unroll
    for (int j = 0; j < HH; j++) {
        float tt = s_b2[j];
#pragma unroll
        for (int k = 0; k < HH; k++) tt = fmaf(h[k], s_w2[k * HH + j], tt);
        fp[j] = pack2(tanh_fast(tt));
    }
#pragma unroll
    for (int d = 0; d < DD; d++) fp[HH + d] = pack2(X[d]);

    // half-assigned bookkeeping
    float4 z = make_float4(0.f, 0.f, 0.f, 0.f);
    float4* ar = (float4*)(g_acc + (size_t)nn * HH) + half * 4;
#pragma unroll
    for (int q = 0; q < 4; q++) ar[q] = z;
    if (half == 0) {
        float* xp = g_X + (size_t)nn * XP;
#pragma unroll
        for (int d = 0; d < DD; d++) xp[d] = X[d];
        xp[13] = 0.f; xp[14] = 0.f; xp[15] = 0.f;
    }

    // this half's 32 k's of (u, v)
    float* up = g_u + (size_t)nn * K1 + half * 32;
    float* vp = g_v + (size_t)nn * K1 + half * 32;
#pragma unroll 1
    for (int k4 = 0; k4 < 8; k4++) {
        float uu[4], vv[4];
#pragma unroll
        for (int j = 0; j < 4; j++) {
            int k = half * 32 + 4 * k4 + j;
            ull a0 = s_cbp[k], a1 = 0ULL;
            const ulonglong2* wr = (const ulonglong2*)(s_wab + k * WABROW);
#pragma unroll
            for (int q = 0; q < 22; q++) {
                ulonglong2 w = wr[q];
                ffma2(a0, fp[2 * q], w.x);
                ffma2(a1, fp[2 * q + 1], w.y);
            }
            ull wl = ((const ull*)(s_wab + k * WABROW))[44];
            ffma2(a0, fp[44], wl);
            unpack2(add2(a0, a1), uu[j], vv[j]);
        }
        *(float4*)(up + 4 * k4) = make_float4(uu[0], uu[1], uu[2], uu[3]);
        *(float4*)(vp + 4 * k4) = make_float4(vv[0], vv[1], vv[2], vv[3]);
    }
}

// ---------------- 5) edge kernel: 2 edges/thread, W2 LDS amortized 2x ----------------
// 64 threads = 2 warps per CTA; each warp owns 64 edges (rows w*64..w*64+63)
__global__ void __launch_bounds__(64)
edge_kernel(const int* __restrict__ ei,
            const float* __restrict__ conv_w2,
            const float* __restrict__ conv_b2,
            int E, int ntiles) {
    __shared__ float s_h1[TILE * H1STRIDE];   // 34816 B
    __shared__ float s_w2[K1 * HH];           // 8192 B
    __shared__ int2  s_idx[TILE];             // 1024 B
    __shared__ ull   s_b2p[HH / 2];

    int tid = threadIdx.x;
    int wid = tid >> 5, lid = tid & 31;
    for (int i = tid; i < K1 * HH; i += 64) s_w2[i] = conv_w2[i];
    if (tid < HH / 2) s_b2p[tid] = ((const ull*)conv_b2)[tid];
    __syncthreads();

    int c4 = lid & 15;        // quad within a row
    int hi16 = lid >> 4;      // which of 2 rows per staging step
    int rbase = wid * 64;     // this warp's row block

    for (int tile = blockIdx.x; tile < ntiles; tile += gridDim.x) {
        int base = tile * TILE + rbase;
        int eA = base + lid, eB = base + lid + 32;
        bool vA = eA < E, vB = eB < E;
        int sA = vA ? ei[eA] : 0;
        int dA = vA ? ei[E + eA] : 0;
        int sB = vB ? ei[eB] : 0;
        int dB = vB ? ei[E + eB] : 0;
        s_idx[rbase + lid]      = make_int2(sA, dA);
        s_idx[rbase + lid + 32] = make_int2(sB, dB);
        __syncwarp();

        // ---- stage this warp's 64 rows (2 rows per step, coalesced) ----
#pragma unroll 8
        for (int s = 0; s < 32; s++) {
            int r = 2 * s + hi16;
            int2 p = s_idx[rbase + r];
            float4 U = ((const float4*)(g_u + (size_t)p.y * K1))[c4];
            float4 V = ((const float4*)(g_v + (size_t)p.x * K1))[c4];
            float4 o;
            o.x = fmaxf(U.x + V.x, 0.f);
            o.y = fmaxf(U.y + V.y, 0.f);
            o.z = fmaxf(U.z + V.z, 0.f);
            o.w = fmaxf(U.w + V.w, 0.f);
            *(float4*)(s_h1 + (rbase + r) * H1STRIDE + 4 * c4) = o;
        }
        __syncwarp();

        // ---- compute 2 edges per thread; W2 row read once serves both ----
        ull h2a[16], h2b[16];
#pragma unroll
        for (int q = 0; q < 16; q++) { h2a[q] = s_b2p[q]; h2b[q] = s_b2p[q]; }

        const float* rowA = s_h1 + (rbase + lid) * H1STRIDE;
        const float* rowB = rowA + 32 * H1STRIDE;
#pragma unroll 2
        for (int q = 0; q < 16; q++) {
            float4 ha = *(const float4*)(rowA + 4 * q);
            float4 hb = *(const float4*)(rowB + 4 * q);
#pragma unroll
            for (int j = 0; j < 4; j++) {
                int k = 4 * q + j;
                float tA = (j == 0) ? ha.x : (j == 1) ? ha.y : (j == 2) ? ha.z : ha.w;
                float tB = (j == 0) ? hb.x : (j == 1) ? hb.y : (j == 2) ? hb.z : hb.w;
                ull pA = pack2(tA), pB = pack2(tB);
                const ulonglong2* wr = (const ulonglong2*)(s_w2 + (k << 5));
#pragma unroll
                for (int i = 0; i < 8; i++) {
                    ulonglong2 w = wr[i];
                    ffma2(h2a[2 * i],     pA, w.x);
                    ffma2(h2a[2 * i + 1], pA, w.y);
                    ffma2(h2b[2 * i],     pB, w.x);
                    ffma2(h2b[2 * i + 1], pB, w.y);
                }
            }
        }

        if (vA) {
            float* ap = g_acc + (size_t)dA * HH;
#pragma unroll
            for (int q = 0; q < 8; q++) {
                float a, b, c, d;
                unpack2(h2a[2 * q], a, b);
                unpack2(h2a[2 * q + 1], c, d);
                red_add_v4(ap + 4 * q, tanh_fast(a), tanh_fast(b),
                           tanh_fast(c), tanh_fast(d));
            }
        }
        if (vB) {
            float* ap = g_acc + (size_t)dB * HH;
#pragma unroll
            for (int q = 0; q < 8; q++) {
                float a, b, c, d;
                unpack2(h2b[2 * q], a, b);
                unpack2(h2b[2 * q + 1], c, d);
                red_add_v4(ap + 4 * q, tanh_fast(a), tanh_fast(b),
                           tanh_fast(c), tanh_fast(d));
            }
        }
        __syncwarp();   // done reading s_h1/s_idx before next tile restage
    }
}

// ---------------- 6) global mean pool ----------------
__global__ void pool_kernel(const int* __restrict__ batch, int n) {
    int nn = blockIdx.x * blockDim.x + threadIdx.x;
    if (nn >= n) return;
    int g = batch[nn];
    const float4* ac = (const float4*)(g_acc + (size_t)nn * HH);
    const float4* xr = (const float4*)(g_X + (size_t)nn * XP);
    float* gs = g_gsum + (size_t)g * (HH + XP);
#pragma unroll
    for (int q = 0; q < 8; q++) {
        float4 v = ac[q];
        red_add_v4(gs + 4 * q, v.x, v.y, v.z, v.w);
    }
#pragma unroll
    for (int q = 0; q < 4; q++) {
        float4 v = xr[q];
        red_add_v4(gs + HH + 4 * q, v.x, v.y, v.z, v.w);
    }
    atomicAdd(&g_gcnt[g], 1);
}

// ---------------- 7) output MLP + sigmoid ----------------
__global__ void out_kernel(const float* __restrict__ w1,
                           const float* __restrict__ b1,
                           const float* __restrict__ w2,
                           const float* __restrict__ b2,
                           float* __restrict__ out, int gcount) {
    int g = blockIdx.x * blockDim.x + threadIdx.x;
    if (g >= gcount) return;
    float cnt = fmaxf((float)g_gcnt[g], 1.f);
    float inv = 1.f / cnt;
    float m[FF];
#pragma unroll
    for (int a = 0; a < FF; a++) m[a] = g_gsum[g * (HH + XP) + a] * inv;
    float o = b2[0];
    for (int h = 0; h < HH; h++) {
        float t = b1[h];
#pragma unroll
        for (int a = 0; a < FF; a++) t = fmaf(m[a], w1[a * HH + h], t);
        o = fmaf(fmaxf(t, 0.f), w2[h], o);
    }
    out[g] = 1.f / (1.f + expf(-o));
}

// ---------------- launch ----------------
extern "C" void kernel_launch(void* const* d_in, const int* in_sizes, int n_in,
                              void* d_out, int out_size) {
    const float* x     = (const float*)d_in[0];
    const int*   ei    = (const int*)d_in[1];
    const int*   batch = (const int*)d_in[2];
    const float* gamma = (const float*)d_in[3];
    const float* beta  = (const float*)d_in[4];
    const float* in_w1 = (const float*)d_in[5];
    const float* in_b1 = (const float*)d_in[6];
    const float* in_w2 = (const float*)d_in[7];
    const float* in_b2 = (const float*)d_in[8];
    const float* cw1   = (const float*)d_in[9];
    const float* cb1   = (const float*)d_in[10];
    const float* cw2   = (const float*)d_in[11];
    const float* cb2   = (const float*)d_in[12];
    const float* ow1   = (const float*)d_in[13];
    const float* ob1   = (const float*)d_in[14];
    const float* ow2   = (const float*)d_in[15];
    const float* ob2   = (const float*)d_in[16];

    int n = in_sizes[0] / DD;
    int E = in_sizes[1] / 2;
    int G = out_size;
    int ntiles = (E + TILE - 1) / TILE;
    int grid = 740;
    if (grid > ntiles) grid = ntiles;

    zero_kernel<<<1, 256>>>();
    bn_stats<<<148, 256>>>(x, n);
    prep_kernel<<<1, 256>>>(cw1, 1.f / (float)n);
    node_kernel<<<(2 * n + 255) / 256, 256>>>(x, gamma, beta, in_w1, in_b1,
                                              in_w2, in_b2, cb1, n);
    edge_kernel<<<grid, 64>>>(ei, cw2, cb2, E, ntiles);
    pool_kernel<<<(n + 255) / 256, 256>>>(batch, n);
    out_kernel<<<1, 128>>>(ow1, ob1, ow2, ob2, (float*)d_out, G);
}

// round 14
// speedup vs baseline: 2.2370x; 2.2370x over previous
#include <cuda_runtime.h>
#include <cuda_fp16.h>

#define DD 13
#define HH 32
#define FF 45
#define XP 16
#define K1 64
#define GG 128
#define NMAX 50000
#define WABROW 92
#define TILE 128
#define AROW 72   // halves per staged A row (64 + 8 pad) = 144B

typedef unsigned long long ull;
typedef unsigned int u32;

// ---------------- device scratch ----------------
__device__ float g_sum[DD];
__device__ float g_sumsq[DD];
__device__ float g_mean[DD];
__device__ float g_istd[DD];
__device__ float g_X[NMAX * XP];
__device__ __align__(256) __half g_u[NMAX * K1];
__device__ __align__(256) __half g_v[NMAX * K1];
__device__ float g_acc[NMAX * HH];
__device__ float g_wab[K1 * WABROW];
__device__ float g_gsum[GG * (HH + XP)];
__device__ int   g_gcnt[GG];

// ---------------- helpers ----------------
__device__ __forceinline__ float tanh_fast(float x) {
    float y; asm("tanh.approx.f32 %0, %1;" : "=f"(y) : "f"(x)); return y;
}
__device__ __forceinline__ void red_add_v4(float* p, float a, float b, float c, float d) {
    asm volatile("red.global.add.v4.f32 [%0], {%1, %2, %3, %4};"
                 :: "l"(p), "f"(a), "f"(b), "f"(c), "f"(d) : "memory");
}
__device__ __forceinline__ void red_add_v2(float* p, float a, float b) {
    asm volatile("red.global.add.v2.f32 [%0], {%1, %2};"
                 :: "l"(p), "f"(a), "f"(b) : "memory");
}
__device__ __forceinline__ ull pack2(float x) {
    ull r; asm("mov.b64 %0, {%1, %1};" : "=l"(r) : "r"(__float_as_uint(x))); return r;
}
__device__ __forceinline__ void ffma2(ull& d, ull a, ull b) {
    asm("fma.rn.f32x2 %0, %1, %2, %0;" : "+l"(d) : "l"(a), "l"(b));
}
__device__ __forceinline__ ull add2(ull a, ull b) {
    ull r; asm("add.rn.f32x2 %0, %1, %2;" : "=l"(r) : "l"(a), "l"(b)); return r;
}
__device__ __forceinline__ void unpack2(ull v, float& lo, float& hi) {
    u32 a, b; asm("mov.b64 {%0, %1}, %2;" : "=r"(a), "=r"(b) : "l"(v));
    lo = __uint_as_float(a); hi = __uint_as_float(b);
}
__device__ __forceinline__ u32 smem_u32(const void* p) {
    u32 a; asm("{ .reg .u64 t; cvta.to.shared.u64 t, %1; cvt.u32.u64 %0, t; }"
               : "=r"(a) : "l"(p));
    return a;
}
__device__ __forceinline__ u32 packh2(float lo, float hi) {
    __half2 h = __floats2half2_rn(lo, hi);
    return *(u32*)&h;
}
__device__ __forceinline__ void ldmA(u32* A, u32 addr) {
    asm volatile("ldmatrix.sync.aligned.m8n8.x4.shared.b16 {%0,%1,%2,%3}, [%4];"
        : "=r"(A[0]), "=r"(A[1]), "=r"(A[2]), "=r"(A[3]) : "r"(addr) : "memory");
}
__device__ __forceinline__ void mma16816(float* c, const u32* a, const u32* b) {
    asm volatile("mma.sync.aligned.m16n8k16.row.col.f32.f16.f16.f32 "
        "{%0,%1,%2,%3}, {%4,%5,%6,%7}, {%8,%9}, {%0,%1,%2,%3};"
        : "+f"(c[0]), "+f"(c[1]), "+f"(c[2]), "+f"(c[3])
        : "r"(a[0]), "r"(a[1]), "r"(a[2]), "r"(a[3]), "r"(b[0]), "r"(b[1]));
}

// ---------------- 1) small zero ----------------
__global__ void zero_kernel() {
    int i = threadIdx.x;
    if (i < DD) { g_sum[i] = 0.f; g_sumsq[i] = 0.f; }
    for (int j = i; j < GG * (HH + XP); j += blockDim.x) g_gsum[j] = 0.f;
    if (i < GG) g_gcnt[i] = 0;
}

// ---------------- 2) batchnorm statistics ----------------
__global__ void bn_stats(const float* __restrict__ x, int n) {
    float s[DD], s2[DD];
#pragma unroll
    for (int d = 0; d < DD; d++) { s[d] = 0.f; s2[d] = 0.f; }
    for (int i = blockIdx.x * blockDim.x + threadIdx.x; i < n;
         i += gridDim.x * blockDim.x) {
#pragma unroll
        for (int d = 0; d < DD; d++) {
            float v = x[i * DD + d];
            s[d] += v; s2[d] += v * v;
        }
    }
#pragma unroll
    for (int d = 0; d < DD; d++) {
        for (int off = 16; off > 0; off >>= 1) {
            s[d]  += __shfl_down_sync(0xffffffffu, s[d], off);
            s2[d] += __shfl_down_sync(0xffffffffu, s2[d], off);
        }
    }
    if ((threadIdx.x & 31) == 0) {
#pragma unroll
        for (int d = 0; d < DD; d++) {
            atomicAdd(&g_sum[d], s[d]);
            atomicAdd(&g_sumsq[d], s2[d]);
        }
    }
}

// ---------------- 3) prep: stats + interleaved combined conv_w1 ----------------
__global__ void prep_kernel(const float* __restrict__ conv_w1, float invN) {
    int tid = threadIdx.x;
    if (tid < DD) {
        float mu  = g_sum[tid] * invN;
        float var = g_sumsq[tid] * invN - mu * mu;
        g_mean[tid] = mu;
        g_istd[tid] = rsqrtf(var + 1e-5f);
    }
    for (int i = tid; i < K1 * (WABROW / 2); i += blockDim.x) {
        int k = i / (WABROW / 2), a = i % (WABROW / 2);
        float wa = 0.f, wb = 0.f;
        if (a < FF) {
            float w0 = conv_w1[a * K1 + k];
            float w1 = conv_w1[(FF + a) * K1 + k];
            wa = w0 - w1; wb = w1;
        }
        g_wab[k * WABROW + 2 * a]     = wa;
        g_wab[k * WABROW + 2 * a + 1] = wb;
    }
}

// ---------------- 4) node kernel: BN + inputnet + u/v (fp16) + zero acc ----------------
__global__ void node_kernel(const float* __restrict__ x,
                            const float* __restrict__ gamma,
                            const float* __restrict__ beta,
                            const float* __restrict__ w1,
                            const float* __restrict__ b1,
                            const float* __restrict__ w2,
                            const float* __restrict__ b2,
                            const float* __restrict__ conv_b1,
                            int n) {
    __shared__ float s_w1[DD * HH], s_w2[HH * HH], s_b1[HH], s_b2[HH];
    __shared__ float s_gam[DD], s_bet[DD], s_mu[DD], s_is[DD];
    __shared__ float s_wab[K1 * WABROW];
    __shared__ ull   s_cbp[K1];
    for (int i = threadIdx.x; i < DD * HH; i += blockDim.x) s_w1[i] = w1[i];
    for (int i = threadIdx.x; i < HH * HH; i += blockDim.x) s_w2[i] = w2[i];
    for (int i = threadIdx.x; i < K1 * WABROW; i += blockDim.x) s_wab[i] = g_wab[i];
    if (threadIdx.x < K1)
        s_cbp[threadIdx.x] = (ull)__float_as_uint(conv_b1[threadIdx.x]);
    if (threadIdx.x < HH) { s_b1[threadIdx.x] = b1[threadIdx.x]; s_b2[threadIdx.x] = b2[threadIdx.x]; }
    if (threadIdx.x < DD) {
        s_gam[threadIdx.x] = gamma[threadIdx.x];
        s_bet[threadIdx.x] = beta[threadIdx.x];
        s_mu[threadIdx.x]  = g_mean[threadIdx.x];
        s_is[threadIdx.x]  = g_istd[threadIdx.x];
    }
    __syncthreads();
    int nn = blockIdx.x * blockDim.x + threadIdx.x;
    if (nn >= n) return;

    float X[DD];
#pragma unroll
    for (int d = 0; d < DD; d++)
        X[d] = (x[nn * DD + d] - s_mu[d]) * s_is[d] * s_gam[d] + s_bet[d];

    float h[HH];
#pragma unroll
    for (int j = 0; j < HH; j++) {
        float t = s_b1[j];
#pragma unroll
        for (int d = 0; d < DD; d++) t = fmaf(X[d], s_w1[d * HH + j], t);
        h[j] = fmaxf(t, 0.f);
    }
    ull fp[FF];
#pragma unroll
    for (int j = 0; j < HH; j++) {
        float t = s_b2[j];
#pragma unroll
        for (int k = 0; k < HH; k++) t = fmaf(h[k], s_w2[k * HH + j], t);
        fp[j] = pack2(tanh_fast(t));
    }
#pragma unroll
    for (int d = 0; d < DD; d++) fp[HH + d] = pack2(X[d]);

    float* xp = g_X + (size_t)nn * XP;
#pragma unroll
    for (int d = 0; d < DD; d++) xp[d] = X[d];
    xp[13] = 0.f; xp[14] = 0.f; xp[15] = 0.f;

    float4 z = make_float4(0.f, 0.f, 0.f, 0.f);
    float4* ar = (float4*)(g_acc + (size_t)nn * HH);
#pragma unroll
    for (int q = 0; q < 8; q++) ar[q] = z;

    __half* up = g_u + (size_t)nn * K1;
    __half* vp = g_v + (size_t)nn * K1;
#pragma unroll 1
    for (int k4 = 0; k4 < K1 / 4; k4++) {
        float uu[4], vv[4];
#pragma unroll
        for (int j = 0; j < 4; j++) {
            int k = 4 * k4 + j;
            ull a0 = s_cbp[k], a1 = 0ULL;
            const ulonglong2* wr = (const ulonglong2*)(s_wab + k * WABROW);
#pragma unroll
            for (int q = 0; q < 22; q++) {
                ulonglong2 w = wr[q];
                ffma2(a0, fp[2 * q], w.x);
                ffma2(a1, fp[2 * q + 1], w.y);
            }
            ull wl = ((const ull*)(s_wab + k * WABROW))[44];
            ffma2(a0, fp[44], wl);
            unpack2(add2(a0, a1), uu[j], vv[j]);
        }
        *(uint2*)(up + 4 * k4) = make_uint2(packh2(uu[0], uu[1]), packh2(uu[2], uu[3]));
        *(uint2*)(vp + 4 * k4) = make_uint2(packh2(vv[0], vv[1]), packh2(vv[2], vv[3]));
    }
}

// ---------------- 5) edge kernel: mma.sync tensor-core, W2 in registers ----------------
__global__ void __launch_bounds__(128)
edge_kernel(const int* __restrict__ ei,
            const float* __restrict__ conv_w2,
            const float* __restrict__ conv_b2,
            int E, int ntiles) {
    __shared__ __align__(16) __half s_a[4][32 * AROW];  // 4 warps x 32 rows x 144B
    __shared__ int s_dst[4][32];

    int tid = threadIdx.x, wid = tid >> 5, lid = tid & 31;
    int c = lid & 3, r4 = lid >> 2;

    // ---- persistent B fragments: W2 fp16 hi + lo, [kc][nc][2] ----
    u32 Bhi[4][4][2], Blo[4][4][2];
#pragma unroll
    for (int kc = 0; kc < 4; kc++)
#pragma unroll
        for (int nc = 0; nc < 4; nc++) {
            int n = nc * 8 + r4;
            int k0 = kc * 16 + 2 * c;
            float w00 = conv_w2[(k0    ) * 32 + n];
            float w01 = conv_w2[(k0 + 1) * 32 + n];
            float w10 = conv_w2[(k0 + 8) * 32 + n];
            float w11 = conv_w2[(k0 + 9) * 32 + n];
            __half h00 = __float2half_rn(w00), h01 = __float2half_rn(w01);
            __half h10 = __float2half_rn(w10), h11 = __float2half_rn(w11);
            Bhi[kc][nc][0] = packh2(__half2float(h00), __half2float(h01));
            Bhi[kc][nc][1] = packh2(__half2float(h10), __half2float(h11));
            Blo[kc][nc][0] = packh2(w00 - __half2float(h00), w01 - __half2float(h01));
            Blo[kc][nc][1] = packh2(w10 - __half2float(h10), w11 - __half2float(h11));
        }
    // per-lane bias for its two columns per nc
    float b2v[4][2];
#pragma unroll
    for (int nc = 0; nc < 4; nc++) {
        b2v[nc][0] = conv_b2[nc * 8 + 2 * c];
        b2v[nc][1] = conv_b2[nc * 8 + 2 * c + 1];
    }

    u32 sa_base = smem_u32(&s_a[wid][0]);
    int rsub = lid >> 3;   // staging: 4 rows per step
    int c8 = lid & 7;      // 8 lanes per row, 8 halves each
    __half2 z2 = __float2half2_rn(0.f);

    for (int tile = blockIdx.x; tile < ntiles; tile += gridDim.x) {
        int base = tile * TILE + wid * 32;
        int e = base + lid;
        bool val = e < E;
        int src = val ? ei[e] : 0;
        int dst = val ? ei[E + e] : 0;
        s_dst[wid][lid] = dst;
        __syncwarp();

        // ---- stage A = fp16 relu(u[dst]+v[src]) rows into SMEM ----
#pragma unroll
        for (int s = 0; s < 8; s++) {
            int row = 4 * s + rsub;
            int dn = __shfl_sync(0xffffffffu, dst, row);
            int sn = __shfl_sync(0xffffffffu, src, row);
            uint4 U = *(const uint4*)(g_u + (size_t)dn * K1 + 8 * c8);
            uint4 V = *(const uint4*)(g_v + (size_t)sn * K1 + 8 * c8);
            uint4 O;
            { __half2 a = __hmax2(__hadd2(*(__half2*)&U.x, *(__half2*)&V.x), z2); O.x = *(u32*)&a; }
            { __half2 a = __hmax2(__hadd2(*(__half2*)&U.y, *(__half2*)&V.y), z2); O.y = *(u32*)&a; }
            { __half2 a = __hmax2(__hadd2(*(__half2*)&U.z, *(__half2*)&V.z), z2); O.z = *(u32*)&a; }
            { __half2 a = __hmax2(__hadd2(*(__half2*)&U.w, *(__half2*)&V.w), z2); O.w = *(u32*)&a; }
            *(uint4*)(&s_a[wid][row * AROW + 8 * c8]) = O;
        }
        __syncwarp();

        // ---- GEMM: 2 M-chunks x 4 N-chunks x 4 K-chunks, hi+lo ----
        float acc[2][4][4];
#pragma unroll
        for (int mi = 0; mi < 2; mi++)
#pragma unroll
            for (int nc = 0; nc < 4; nc++)
#pragma unroll
                for (int q = 0; q < 4; q++) acc[mi][nc][q] = 0.f;

        int g = lid >> 3, lr = lid & 7;
#pragma unroll
        for (int kc = 0; kc < 4; kc++) {
            u32 A[2][4];
#pragma unroll
            for (int mi = 0; mi < 2; mi++) {
                int row = mi * 16 + lr + (g & 1) * 8;
                u32 addr = sa_base + (u32)(row * (AROW * 2) + kc * 32 + (g >> 1) * 16);
                ldmA(A[mi], addr);
            }
#pragma unroll
            for (int mi = 0; mi < 2; mi++)
#pragma unroll
                for (int nc = 0; nc < 4; nc++) {
                    mma16816(acc[mi][nc], A[mi], Bhi[kc][nc]);
                    mma16816(acc[mi][nc], A[mi], Blo[kc][nc]);
                }
        }

        // ---- epilogue: bias + tanh + scatter red.v2 ----
#pragma unroll
        for (int mi = 0; mi < 2; mi++) {
            int rl0 = mi * 16 + r4, rl1 = rl0 + 8;
            int d0 = s_dst[wid][rl0], d1 = s_dst[wid][rl1];
            bool v0 = (base + rl0) < E, v1 = (base + rl1) < E;
#pragma unroll
            for (int nc = 0; nc < 4; nc++) {
                float x0 = tanh_fast(acc[mi][nc][0] + b2v[nc][0]);
                float x1 = tanh_fast(acc[mi][nc][1] + b2v[nc][1]);
                float x2 = tanh_fast(acc[mi][nc][2] + b2v[nc][0]);
                float x3 = tanh_fast(acc[mi][nc][3] + b2v[nc][1]);
                if (v0) red_add_v2(g_acc + (size_t)d0 * HH + nc * 8 + 2 * c, x0, x1);
                if (v1) red_add_v2(g_acc + (size_t)d1 * HH + nc * 8 + 2 * c, x2, x3);
            }
        }
        __syncwarp();
    }
}

// ---------------- 6) global mean pool ----------------
__global__ void pool_kernel(const int* __restrict__ batch, int n) {
    int nn = blockIdx.x * blockDim.x + threadIdx.x;
    if (nn >= n) return;
    int g = batch[nn];
    const float4* ac = (const float4*)(g_acc + (size_t)nn * HH);
    const float4* xr = (const float4*)(g_X + (size_t)nn * XP);
    float* gs = g_gsum + (size_t)g * (HH + XP);
#pragma unroll
    for (int q = 0; q < 8; q++) {
        float4 v = ac[q];
        red_add_v4(gs + 4 * q, v.x, v.y, v.z, v.w);
    }
#pragma unroll
    for (int q = 0; q < 4; q++) {
        float4 v = xr[q];
        red_add_v4(gs + HH + 4 * q, v.x, v.y, v.z, v.w);
    }
    atomicAdd(&g_gcnt[g], 1);
}

// ---------------- 7) output MLP + sigmoid ----------------
__global__ void out_kernel(const float* __restrict__ w1,
                           const float* __restrict__ b1,
                           const float* __restrict__ w2,
                           const float* __restrict__ b2,
                           float* __restrict__ out, int gcount) {
    int g = blockIdx.x * blockDim.x + threadIdx.x;
    if (g >= gcount) return;
    float cnt = fmaxf((float)g_gcnt[g], 1.f);
    float inv = 1.f / cnt;
    float m[FF];
#pragma unroll
    for (int a = 0; a < FF; a++) m[a] = g_gsum[g * (HH + XP) + a] * inv;
    float o = b2[0];
    for (int h = 0; h < HH; h++) {
        float t = b1[h];
#pragma unroll
        for (int a = 0; a < FF; a++) t = fmaf(m[a], w1[a * HH + h], t);
        o = fmaf(fmaxf(t, 0.f), w2[h], o);
    }
    out[g] = 1.f / (1.f + expf(-o));
}

// ---------------- launch ----------------
extern "C" void kernel_launch(void* const* d_in, const int* in_sizes, int n_in,
                              void* d_out, int out_size) {
    const float* x     = (const float*)d_in[0];
    const int*   ei    = (const int*)d_in[1];
    const int*   batch = (const int*)d_in[2];
    const float* gamma = (const float*)d_in[3];
    const float* beta  = (const float*)d_in[4];
    const float* in_w1 = (const float*)d_in[5];
    const float* in_b1 = (const float*)d_in[6];
    const float* in_w2 = (const float*)d_in[7];
    const float* in_b2 = (const float*)d_in[8];
    const float* cw1   = (const float*)d_in[9];
    const float* cb1   = (const float*)d_in[10];
    const float* cw2   = (const float*)d_in[11];
    const float* cb2   = (const float*)d_in[12];
    const float* ow1   = (const float*)d_in[13];
    const float* ob1   = (const float*)d_in[14];
    const float* ow2   = (const float*)d_in[15];
    const float* ob2   = (const float*)d_in[16];

    int n = in_sizes[0] / DD;
    int E = in_sizes[1] / 2;
    int G = out_size;
    int ntiles = (E + TILE - 1) / TILE;
    int grid = 444;
    if (grid > ntiles) grid = ntiles;

    zero_kernel<<<1, 256>>>();
    bn_stats<<<148, 256>>>(x, n);
    prep_kernel<<<1, 256>>>(cw1, 1.f / (float)n);
    node_kernel<<<(n + 127) / 128, 128>>>(x, gamma, beta, in_w1, in_b1,
                                          in_w2, in_b2, cb1, n);
    edge_kernel<<<grid, 128>>>(ei, cw2, cb2, E, ntiles);
    pool_kernel<<<(n + 255) / 256, 256>>>(batch, n);
    out_kernel<<<1, 128>>>(ow1, ob1, ow2, ob2, (float*)d_out, G);
}